// round 1
// baseline (speedup 1.0000x reference)
#include <cuda_runtime.h>
#include <math.h>
#include <stdint.h>

// DynamicRoutingLayer: B=256, N=512, E=64, O=64, K=8, 3 softmax passes.
// One CTA per batch b. cc_0 streamed from HBM 3x; routing delta d[k][n] kept
// in shared. priors computed in-kernel into shared (padded stride 66 to make
// the sim-pass dot products bank-conflict-free).

#define BB 256
#define NN 512
#define EE 64
#define OO 64
#define KK 8
#define PSTR 66              // padded row stride for p, z, v in shared
#define THREADS 1024

// shared layout (floats)
#define P_OFF   0                       // p[N][PSTR]
#define D_OFF   (NN * PSTR)             // d[K][N]
#define S_OFF   (D_OFF + KK * NN)       // S[E][O]
#define Z_OFF   (S_OFF + EE * OO)       // z[K][PSTR]
#define V_OFF   (Z_OFF + KK * PSTR)     // v[K][PSTR]
#define SMEM_FLOATS (V_OFF + KK * PSTR)
#define SMEM_BYTES (SMEM_FLOATS * 4)

__global__ __launch_bounds__(THREADS, 1)
void routing_kernel(const float* __restrict__ emb,
                    const float* __restrict__ S,
                    const float* __restrict__ cc,
                    float* __restrict__ out)
{
    extern __shared__ float sm[];
    float* p   = sm + P_OFF;
    float* d   = sm + D_OFF;
    float* Ssh = sm + S_OFF;
    float* z   = sm + Z_OFF;
    float* v   = sm + V_OFF;

    const int b    = blockIdx.x;
    const int tid  = threadIdx.x;
    const int warp = tid >> 5;
    const int lane = tid & 31;

    // ---- init: load S, zero d ----
    for (int i = tid; i < EE * OO; i += THREADS) Ssh[i] = S[i];
    for (int i = tid; i < KK * NN; i += THREADS) d[i] = 0.0f;
    __syncthreads();

    // ---- Phase A: priors p[n][o] = emb[b,n,:] @ S[:,o] ----
    // warp-uniform n (broadcast LDG of emb rows), lane covers o-pair.
    {
        const int o2 = lane * 2;
        const float* embb = emb + (size_t)b * (NN * EE);
        for (int g = warp; g < NN / 4; g += 32) {
            const int n0 = g * 4;
            const float4* r0 = (const float4*)(embb + (size_t)(n0 + 0) * EE);
            const float4* r1 = (const float4*)(embb + (size_t)(n0 + 1) * EE);
            const float4* r2 = (const float4*)(embb + (size_t)(n0 + 2) * EE);
            const float4* r3 = (const float4*)(embb + (size_t)(n0 + 3) * EE);
            float2 a0 = make_float2(0.f, 0.f), a1 = a0, a2 = a0, a3 = a0;
            #pragma unroll
            for (int e4 = 0; e4 < EE / 4; e4++) {
                float4 x0 = r0[e4], x1 = r1[e4], x2 = r2[e4], x3 = r3[e4];
                const float* sb = &Ssh[e4 * 4 * OO + o2];
                float2 s0 = *(const float2*)(sb);
                float2 s1 = *(const float2*)(sb + OO);
                float2 s2 = *(const float2*)(sb + 2 * OO);
                float2 s3 = *(const float2*)(sb + 3 * OO);
                a0.x += x0.x*s0.x; a0.y += x0.x*s0.y;
                a1.x += x1.x*s0.x; a1.y += x1.x*s0.y;
                a2.x += x2.x*s0.x; a2.y += x2.x*s0.y;
                a3.x += x3.x*s0.x; a3.y += x3.x*s0.y;

                a0.x += x0.y*s1.x; a0.y += x0.y*s1.y;
                a1.x += x1.y*s1.x; a1.y += x1.y*s1.y;
                a2.x += x2.y*s1.x; a2.y += x2.y*s1.y;
                a3.x += x3.y*s1.x; a3.y += x3.y*s1.y;

                a0.x += x0.z*s2.x; a0.y += x0.z*s2.y;
                a1.x += x1.z*s2.x; a1.y += x1.z*s2.y;
                a2.x += x2.z*s2.x; a2.y += x2.z*s2.y;
                a3.x += x3.z*s2.x; a3.y += x3.z*s2.y;

                a0.x += x0.w*s3.x; a0.y += x0.w*s3.y;
                a1.x += x1.w*s3.x; a1.y += x1.w*s3.y;
                a2.x += x2.w*s3.x; a2.y += x2.w*s3.y;
                a3.x += x3.w*s3.x; a3.y += x3.w*s3.y;
            }
            *(float2*)&p[(n0 + 0) * PSTR + o2] = a0;
            *(float2*)&p[(n0 + 1) * PSTR + o2] = a1;
            *(float2*)&p[(n0 + 2) * PSTR + o2] = a2;
            *(float2*)&p[(n0 + 3) * PSTR + o2] = a3;
        }
    }
    __syncthreads();

    // ---- Phase B: 3 softmax passes ----
    const size_t ccbase = (size_t)b * KK * NN * OO;
    const int o0 = lane * 2;

    #pragma unroll 1
    for (int t = 0; t < 3; t++) {
        // zero z
        for (int i = tid; i < KK * PSTR; i += THREADS) z[i] = 0.0f;
        __syncthreads();

        // accumulate z[k][o] over n; each warp owns 16 n rows, lane owns o-pair
        float za[16];
        #pragma unroll
        for (int i = 0; i < 16; i++) za[i] = 0.0f;

        for (int n = warp * 16; n < warp * 16 + 16; n++) {
            float sx[KK], sy[KK];
            #pragma unroll
            for (int k = 0; k < KK; k++) {
                float2 c2 = *(const float2*)(cc + ccbase + (size_t)(k * NN + n) * OO + o0);
                float dk = d[(k << 9) + n];
                sx[k] = c2.x + dk;
                sy[k] = c2.y + dk;
            }
            float mx = sx[0], my = sy[0];
            #pragma unroll
            for (int k = 1; k < KK; k++) { mx = fmaxf(mx, sx[k]); my = fmaxf(my, sy[k]); }
            float dx = 0.0f, dy = 0.0f;
            #pragma unroll
            for (int k = 0; k < KK; k++) {
                sx[k] = __expf(sx[k] - mx); dx += sx[k];
                sy[k] = __expf(sy[k] - my); dy += sy[k];
            }
            float2 p2 = *(const float2*)&p[n * PSTR + o0];
            float wx = p2.x * __fdividef(1.0f, dx);
            float wy = p2.y * __fdividef(1.0f, dy);
            #pragma unroll
            for (int k = 0; k < KK; k++) {
                za[2 * k]     += sx[k] * wx;
                za[2 * k + 1] += sy[k] * wy;
            }
        }
        #pragma unroll
        for (int k = 0; k < KK; k++) {
            atomicAdd(&z[k * PSTR + o0],     za[2 * k]);
            atomicAdd(&z[k * PSTR + o0 + 1], za[2 * k + 1]);
        }
        __syncthreads();

        // squash: warps 0..7, one per k
        if (warp < KK) {
            const int k = warp;
            float z0 = z[k * PSTR + lane];
            float z1 = z[k * PSTR + lane + 32];
            float sq = z0 * z0 + z1 * z1;
            #pragma unroll
            for (int off = 16; off > 0; off >>= 1)
                sq += __shfl_xor_sync(0xffffffffu, sq, off);
            float c = sq / ((1.0f + sq) * sqrtf(sq + 1e-9f));
            if (t == 2) {
                float* ob = out + ((size_t)b * KK + k) * OO;
                ob[lane]      = c * z0;
                ob[lane + 32] = c * z1;
            } else {
                v[k * PSTR + lane]      = c * z0;
                v[k * PSTR + lane + 32] = c * z1;
            }
        }
        if (t == 2) break;
        __syncthreads();

        // sim pass: d[k][n] += sum_o p[n][o] * v[k][o]
        // lane -> (k = lane&7, dn = lane>>3); warp covers 4 n per iter, 4 iters
        {
            const int k  = lane & 7;
            const int dn = lane >> 3;
            #pragma unroll
            for (int it = 0; it < 4; it++) {
                const int n = (warp + (it << 5)) * 4 + dn;
                const float2* pr = (const float2*)&p[n * PSTR];
                const float2* vr = (const float2*)&v[k * PSTR];
                float acc = 0.0f;
                #pragma unroll
                for (int o2i = 0; o2i < OO / 2; o2i++) {
                    float2 pp = pr[o2i];
                    float2 vv = vr[o2i];
                    acc += pp.x * vv.x + pp.y * vv.y;
                }
                d[(k << 9) + n] += acc;
            }
        }
        __syncthreads();
    }
}

extern "C" void kernel_launch(void* const* d_in, const int* in_sizes, int n_in,
                              void* d_out, int out_size)
{
    // identify inputs by size for robustness
    const float* emb = nullptr;  // 256*512*64  = 8388608
    const float* S   = nullptr;  // 64*64       = 4096
    const float* cc  = nullptr;  // 256*8*512*64= 67108864
    for (int i = 0; i < n_in; i++) {
        if (in_sizes[i] == 8388608)       emb = (const float*)d_in[i];
        else if (in_sizes[i] == 4096)     S   = (const float*)d_in[i];
        else if (in_sizes[i] == 67108864) cc  = (const float*)d_in[i];
    }
    float* out = (float*)d_out;

    cudaFuncSetAttribute(routing_kernel,
                         cudaFuncAttributeMaxDynamicSharedMemorySize, SMEM_BYTES);
    routing_kernel<<<BB, THREADS, SMEM_BYTES>>>(emb, S, cc, out);
}